// round 14
// baseline (speedup 1.0000x reference)
#include <cuda_runtime.h>
#include <cuda_bf16.h>
#include <cuda.h>
#include <cstdint>

#define CIN 64
#define COUT 64
#define HW 32
#define KTOT 576
#define KT 32
#define NTILES 18
#define XR 40                              // bf16 per X row (80B, ldmatrix conflict-free)

#define W_POS_BYTES 8192                   // 64 co x 128B (SW128)
#define W_ALL_BYTES 16384                  // 2 pos
#define X_ARR_BYTES 2560                   // 32 rows x 80B
#define X_POS_BYTES 5120                   // hi + lo
#define STAGE_BYTES 26624                  // W_ALL + 2*X_POS
#define OFF_VOFF   53248                   // 2 stages end
#define OFF_SBIAS  56320                   // voff: 768 int
#define OFF_MBAR   56832                   // sbias: 128 float
#define SMEM_TOTAL 56848

// x as bf16 hi/lo, layout [ci][h][w][b] (b innermost, 64B rows)
__device__ __nv_bfloat16 g_xh[CIN * HW * HW * 32];
__device__ __nv_bfloat16 g_xl[CIN * HW * HW * 32];

__global__ void transpose_x_kernel(const float* __restrict__ x) {
    __shared__ float tile[32][33];
    int cih = blockIdx.x;
    int lane = threadIdx.x & 31;
    int grp  = threadIdx.x >> 5;
    const float* src = x + (size_t)cih * 32;
#pragma unroll
    for (int i = 0; i < 4; ++i) {
        int b = grp + 8 * i;
        tile[b][lane] = src[(size_t)b * 65536 + lane];
    }
    __syncthreads();
    size_t base = (size_t)cih * 1024;
#pragma unroll
    for (int i = 0; i < 4; ++i) {
        int w = grp + 8 * i;
        float v = tile[lane][w];
        __nv_bfloat16 h = __float2bfloat16(v);
        __nv_bfloat16 l = __float2bfloat16(v - __bfloat162float(h));
        g_xh[base + w * 32 + lane] = h;
        g_xl[base + w * 32 + lane] = l;
    }
}

__device__ __forceinline__ uint32_t smem_u32(const void* p) {
    uint32_t a;
    asm("{ .reg .u64 t; cvta.to.shared.u64 t, %1; cvt.u32.u64 %0, t; }" : "=r"(a) : "l"(p));
    return a;
}

// hi = top-16 truncation of pair (f0=low element), lo = bf16(f - hi) pair
__device__ __forceinline__ void split_pair(float f0, float f1, uint32_t& hi2, uint32_t& lo2) {
    asm("prmt.b32 %0, %1, %2, 0x7632;" : "=r"(hi2) : "r"(__float_as_uint(f0)), "r"(__float_as_uint(f1)));
    float h0 = __uint_as_float(__float_as_uint(f0) & 0xFFFF0000u);
    float h1 = __uint_as_float(__float_as_uint(f1) & 0xFFFF0000u);
    asm("cvt.rn.bf16x2.f32 %0, %1, %2;" : "=r"(lo2) : "f"(f1 - h1), "f"(f0 - h0));
}

#define MMA16(d, a, b) \
    asm volatile("mma.sync.aligned.m16n8k16.row.col.f32.bf16.bf16.f32 " \
        "{%0,%1,%2,%3}, {%4,%5,%6,%7}, {%8,%9}, {%0,%1,%2,%3};" \
        : "+f"(d[0]), "+f"(d[1]), "+f"(d[2]), "+f"(d[3]) \
        : "r"(a[0]), "r"(a[1]), "r"(a[2]), "r"(a[3]), "r"(b[0]), "r"(b[1]))

#define LDSMT4(r, a) \
    asm volatile("ldmatrix.sync.aligned.m8n8.x4.trans.shared.b16 {%0,%1,%2,%3}, [%4];" \
        : "=r"(r[0]), "=r"(r[1]), "=r"(r[2]), "=r"(r[3]) : "r"(a))

#define CPA16(dst, src, sz) \
    asm volatile("cp.async.cg.shared.global [%0], [%1], 16, %2;" \
        :: "r"(dst), "l"(src), "r"(sz) : "memory")
#define CPA_COMMIT() asm volatile("cp.async.commit_group;" ::: "memory")
#define CPA_WAIT1()  asm volatile("cp.async.wait_group 1;" ::: "memory")
#define CPA_WAIT0()  asm volatile("cp.async.wait_group 0;" ::: "memory")

__global__ __launch_bounds__(256, 4)
void local2d_mma(const __grid_constant__ CUtensorMap tmap,
                 const float* __restrict__ bias,  // [co][pos]
                 float* __restrict__ out)         // [b][co][pos]
{
    extern __shared__ __align__(1024) uint8_t dyn[];
    int*   voff  = (int*)(dyn + OFF_VOFF);    // [u=ci*3+ki][j=kj+pg]
    float* sbias = (float*)(dyn + OFF_SBIAS); // [pg][co]

    int tid = threadIdx.x;
    int pg = tid >> 7;                 // position within CTA (0..1)
    int ptid = tid & 127;
    int lane = tid & 31;
    int nh = ptid >> 5;                // n-tile group within position (0..3)
    int g = lane >> 2, tq = lane & 3;

    int bx = blockIdx.x;
    int y = bx >> 4, x0 = (bx & 15) * 2;
    int pos0 = y * 32 + x0;

    // ---- voff table: [192 u][4 j] ----
    for (int idx = tid; idx < 768; idx += 256) {
        int u = idx >> 2, j = idx & 3;
        int ci = u / 3, ki = u - ci * 3;
        int iy = y + ki - 1, ix = x0 - 1 + j;
        voff[idx] = ((unsigned)iy < 32u && (unsigned)ix < 32u)
                      ? ((ci * 32 + iy) * 32 + ix) * 32 : -1;
    }
    if (tid < 128) sbias[tid] = bias[(size_t)(tid & 63) * 1024 + pos0 + (tid >> 6)];

    uint32_t dyn_a = smem_u32(dyn);
    uint32_t mb0 = dyn_a + OFF_MBAR;
    if (tid == 0) {
        asm volatile("mbarrier.init.shared.b64 [%0], %1;" :: "r"(mb0), "r"(1) : "memory");
        asm volatile("mbarrier.init.shared.b64 [%0], %1;" :: "r"(mb0 + 8), "r"(1) : "memory");
    }
    __syncthreads();

    // X staging constants (per-pos 128 threads: 32 rows x 4 chunks)
    int xrow = (ptid >> 2) & 31;
    int xch  = ptid & 3;

    auto issue = [&](int t) {
        int s = t & 1;
        uint32_t sbase = dyn_a + (uint32_t)s * STAGE_BYTES;
        if (tid == 0) {
            uint32_t mb = mb0 + 8 * s;
            asm volatile("mbarrier.arrive.expect_tx.shared.b64 _, [%0], %1;"
                         :: "r"(mb), "r"(W_ALL_BYTES) : "memory");
            asm volatile(
                "cp.async.bulk.tensor.2d.shared::cta.global.tile.mbarrier::complete_tx::bytes "
                "[%0], [%1, {%2, %3}], [%4];"
                :: "r"(sbase), "l"(&tmap), "r"(t * KT), "r"(pos0 * 64), "r"(mb) : "memory");
        }
        int K = t * KT + xrow;
        int u = (int)(((unsigned)K * 0xAAABu) >> 17);   // K/3
        int j = K - u * 3 + pg;
        int off = voff[u * 4 + j];
        const __nv_bfloat16* sh = g_xh + (off < 0 ? 0 : off) + xch * 8;
        const __nv_bfloat16* sl = g_xl + (off < 0 ? 0 : off) + xch * 8;
        int sz = off < 0 ? 0 : 16;
        uint32_t xb = sbase + W_ALL_BYTES + (uint32_t)pg * X_POS_BYTES
                      + (uint32_t)(xrow * XR + xch * 8) * 2;
        CPA16(xb, sh, sz);
        CPA16(xb + X_ARR_BYTES, sl, sz);
    };

    float acc[2][2][4];
#pragma unroll
    for (int mt = 0; mt < 2; ++mt)
#pragma unroll
        for (int n = 0; n < 2; ++n)
#pragma unroll
            for (int c = 0; c < 4; ++c) acc[mt][n][c] = 0.f;

    issue(0); CPA_COMMIT();
    issue(1); CPA_COMMIT();

    // t-invariant fragment offsets
    uint32_t a_off[2][2];    // [k16][mt], relative to X pos block (hi)
#pragma unroll
    for (int k16 = 0; k16 < 2; ++k16) {
        int lrow = k16 * 16 + ((lane & 16) >> 1) + (lane & 7);
#pragma unroll
        for (int mt = 0; mt < 2; ++mt)
            a_off[k16][mt] = (uint32_t)(lrow * XR + mt * 16 + (lane & 8)) * 2;
    }
    uint32_t b_off[2][2][2]; // [k16][n][ko], relative to W pos block
    int co_n[2];
#pragma unroll
    for (int n = 0; n < 2; ++n) {
        co_n[n] = (nh * 2 + n) * 8 + g;
#pragma unroll
        for (int k16 = 0; k16 < 2; ++k16)
#pragma unroll
            for (int ko = 0; ko < 2; ++ko)
                b_off[k16][n][ko] = (uint32_t)co_n[n] * 128
                    + (uint32_t)((((k16 * 16 + 2 * tq) * 4) + ko * 32) ^ ((co_n[n] & 7) << 4));
    }

    for (int t = 0; t < NTILES; ++t) {
        int s = t & 1;
        uint32_t sbase = dyn_a + (uint32_t)s * STAGE_BYTES;
        uint32_t sbW = sbase + (uint32_t)pg * W_POS_BYTES;
        uint32_t sbX = sbase + W_ALL_BYTES + (uint32_t)pg * X_POS_BYTES;

        if (tid < 32) {   // warp 0 polls TMA mbarrier
            uint32_t mb = mb0 + 8 * s;
            uint32_t ph = (t >> 1) & 1;
            asm volatile(
                "{ .reg .pred P;\n\t"
                "WL%=: mbarrier.try_wait.parity.acquire.cta.shared::cta.b64 P, [%0], %1, 0x989680;\n\t"
                "@P bra WD%=;\n\t"
                "bra WL%=;\n\t"
                "WD%=: }"
                :: "r"(mb), "r"(ph) : "memory");
        }
        CPA_WAIT1();
        __syncthreads();

#pragma unroll
        for (int k16 = 0; k16 < 2; ++k16) {
            uint32_t ah[2][4], al[2][4];
#pragma unroll
            for (int mt = 0; mt < 2; ++mt) {
                uint32_t a_addr = sbX + a_off[k16][mt];
                LDSMT4(ah[mt], a_addr);
                LDSMT4(al[mt], a_addr + X_ARR_BYTES);
            }
#pragma unroll
            for (int n = 0; n < 2; ++n) {
                uint32_t bh[2], bl[2];
#pragma unroll
                for (int ko = 0; ko < 2; ++ko) {
                    float2 f;
                    asm volatile("ld.shared.v2.f32 {%0, %1}, [%2];"
                                 : "=f"(f.x), "=f"(f.y) : "r"(sbW + b_off[k16][n][ko]));
                    split_pair(f.x, f.y, bh[ko], bl[ko]);
                }
#pragma unroll
                for (int mt = 0; mt < 2; ++mt) {
                    MMA16(acc[mt][n], ah[mt], bh);   // hi*hi
                    MMA16(acc[mt][n], ah[mt], bl);   // hi*lo
                    MMA16(acc[mt][n], al[mt], bh);   // lo*hi
                }
            }
        }
        __syncthreads();   // all reads of stage s done before refill
        if (t + 2 < NTILES) issue(t + 2);
        CPA_COMMIT();
    }

    // ---- epilogue: smem transpose to [b*64+co][pos2], coalesced STG.64 ----
    CPA_WAIT0();
    __syncthreads();
    float* ex = (float*)dyn;   // 16 KB
#pragma unroll
    for (int mt = 0; mt < 2; ++mt)
#pragma unroll
        for (int n = 0; n < 2; ++n)
#pragma unroll
            for (int c = 0; c < 4; ++c) {
                int b  = mt * 16 + ((c >> 1) << 3) + g;
                int co = (nh * 2 + n) * 8 + 2 * tq + (c & 1);
                ex[(b * 64 + co) * 2 + pg] = acc[mt][n][c] + sbias[pg * 64 + co];
            }
    __syncthreads();
#pragma unroll
    for (int i = 0; i < 8; ++i) {
        int bc = tid + 256 * i;
        float2 v = *(const float2*)(ex + bc * 2);
        *(float2*)(out + (size_t)bc * 1024 + pos0) = v;
    }
}

typedef CUresult (*EncodeTiledFn)(
    CUtensorMap*, CUtensorMapDataType, cuuint32_t, void*,
    const cuuint64_t*, const cuuint64_t*, const cuuint32_t*, const cuuint32_t*,
    CUtensorMapInterleave, CUtensorMapSwizzle, CUtensorMapL2promotion,
    CUtensorMapFloatOOBfill);

extern "C" void kernel_launch(void* const* d_in, const int* in_sizes, int n_in,
                              void* d_out, int out_size) {
    const float* x    = (const float*)d_in[0];
    const float* wgt  = (const float*)d_in[1];
    const float* bias = (const float*)d_in[2];
    float* out = (float*)d_out;

    void* fn = nullptr;
    cudaDriverEntryPointQueryResult qr;
    cudaGetDriverEntryPoint("cuTensorMapEncodeTiled", &fn, cudaEnableDefault, &qr);
    CUtensorMap tmap;
    cuuint64_t dims[2]    = {576, 65536};
    cuuint64_t strides[1] = {576 * 4};
    cuuint32_t box[2]     = {32, 128};     // 32 k x 128 rows (2 pos x 64 co)
    cuuint32_t es[2]      = {1, 1};
    ((EncodeTiledFn)fn)(&tmap, CU_TENSOR_MAP_DATA_TYPE_FLOAT32, 2, (void*)wgt,
                        dims, strides, box, es,
                        CU_TENSOR_MAP_INTERLEAVE_NONE, CU_TENSOR_MAP_SWIZZLE_128B,
                        CU_TENSOR_MAP_L2_PROMOTION_L2_128B,
                        CU_TENSOR_MAP_FLOAT_OOB_FILL_NONE);

    cudaFuncSetAttribute(local2d_mma, cudaFuncAttributeMaxDynamicSharedMemorySize, SMEM_TOTAL);
    transpose_x_kernel<<<CIN * HW, 256>>>(x);
    local2d_mma<<<512, 256, SMEM_TOTAL>>>(tmap, bias, out);
}

// round 15
// speedup vs baseline: 1.0515x; 1.0515x over previous
#include <cuda_runtime.h>
#include <cuda_fp16.h>
#include <cuda.h>
#include <cstdint>

#define CIN 64
#define COUT 64
#define HW 32
#define KTOT 576
#define KT 32
#define NTILES 18
#define XR 40                              // fp16 per X row (80B, ldmatrix conflict-free)

#define W_POS_BYTES 8192                   // 64 co x 128B (SW128)
#define W_ALL_BYTES 32768                  // 4 pos
#define X_ARR_BYTES 2560                   // 32 rows x 80B
#define X_POS_BYTES 5120                   // hi + lo
#define STAGE_BYTES 53248                  // W_ALL + 4*X_POS
#define OFF_VOFF   106496                  // 2 stages end
#define OFF_SBIAS  111104                  // voff: 1152 int
#define OFF_MBAR   112128                  // sbias: 256 float
#define SMEM_TOTAL 112144

// x as fp16 hi/lo, layout [ci][h][w][b] (b innermost, 64B rows)
__device__ __half g_xh[CIN * HW * HW * 32];
__device__ __half g_xl[CIN * HW * HW * 32];

__global__ void transpose_x_kernel(const float* __restrict__ x) {
    __shared__ float tile[32][33];
    int cih = blockIdx.x;
    int lane = threadIdx.x & 31;
    int grp  = threadIdx.x >> 5;
    const float* src = x + (size_t)cih * 32;
#pragma unroll
    for (int i = 0; i < 4; ++i) {
        int b = grp + 8 * i;
        tile[b][lane] = src[(size_t)b * 65536 + lane];
    }
    __syncthreads();
    size_t base = (size_t)cih * 1024;
#pragma unroll
    for (int i = 0; i < 4; ++i) {
        int w = grp + 8 * i;
        float v = tile[lane][w];
        __half h = __float2half_rn(v);
        __half l = __float2half_rn(v - __half2float(h));
        g_xh[base + w * 32 + lane] = h;
        g_xl[base + w * 32 + lane] = l;
    }
}

__device__ __forceinline__ uint32_t smem_u32(const void* p) {
    uint32_t a;
    asm("{ .reg .u64 t; cvta.to.shared.u64 t, %1; cvt.u32.u64 %0, t; }" : "=r"(a) : "l"(p));
    return a;
}

#define MMAH(d, a, b) \
    asm volatile("mma.sync.aligned.m16n8k16.row.col.f32.f16.f16.f32 " \
        "{%0,%1,%2,%3}, {%4,%5,%6,%7}, {%8,%9}, {%0,%1,%2,%3};" \
        : "+f"(d[0]), "+f"(d[1]), "+f"(d[2]), "+f"(d[3]) \
        : "r"(a[0]), "r"(a[1]), "r"(a[2]), "r"(a[3]), "r"(b[0]), "r"(b[1]))

#define LDSMT4(r, a) \
    asm volatile("ldmatrix.sync.aligned.m8n8.x4.trans.shared.b16 {%0,%1,%2,%3}, [%4];" \
        : "=r"(r[0]), "=r"(r[1]), "=r"(r[2]), "=r"(r[3]) : "r"(a))

#define CPA16(dst, src, sz) \
    asm volatile("cp.async.cg.shared.global [%0], [%1], 16, %2;" \
        :: "r"(dst), "l"(src), "r"(sz) : "memory")
#define CPA_COMMIT() asm volatile("cp.async.commit_group;" ::: "memory")
#define CPA_WAIT1()  asm volatile("cp.async.wait_group 1;" ::: "memory")
#define CPA_WAIT0()  asm volatile("cp.async.wait_group 0;" ::: "memory")

__global__ __launch_bounds__(512, 2)
void local2d_mma(const __grid_constant__ CUtensorMap tmap,
                 const float* __restrict__ bias,  // [co][pos]
                 float* __restrict__ out)         // [b][co][pos]
{
    extern __shared__ __align__(1024) uint8_t dyn[];
    int*   voff  = (int*)(dyn + OFF_VOFF);    // [u=ci*3+ki][j=kj+pg]
    float* sbias = (float*)(dyn + OFF_SBIAS); // [pg][co]

    int tid = threadIdx.x;
    int pg = tid >> 7;                 // position within CTA (0..3)
    int ptid = tid & 127;
    int lane = tid & 31;
    int nh = ptid >> 5;                // n-tile group within position
    int g = lane >> 2, tq = lane & 3;

    int bx = blockIdx.x;
    int y = bx >> 3, x0 = (bx & 7) * 4;
    int pos0 = y * 32 + x0;

    // ---- voff table: [192 u][6 j] ----
    for (int idx = tid; idx < 1152; idx += 512) {
        int u = idx / 6, j = idx - u * 6;
        int ci = u / 3, ki = u - ci * 3;
        int iy = y + ki - 1, ix = x0 - 1 + j;
        voff[idx] = ((unsigned)iy < 32u && (unsigned)ix < 32u)
                      ? ((ci * 32 + iy) * 32 + ix) * 32 : -1;
    }
    if (tid < 256) sbias[tid] = bias[(size_t)(tid & 63) * 1024 + pos0 + (tid >> 6)];

    uint32_t dyn_a = smem_u32(dyn);
    uint32_t mb0 = dyn_a + OFF_MBAR;
    if (tid == 0) {
        asm volatile("mbarrier.init.shared.b64 [%0], %1;" :: "r"(mb0), "r"(1) : "memory");
        asm volatile("mbarrier.init.shared.b64 [%0], %1;" :: "r"(mb0 + 8), "r"(1) : "memory");
    }
    __syncthreads();

    // X staging constants (this thread stages one 16B chunk of hi and lo)
    int xrow = (ptid >> 2) & 31;
    int xch  = ptid & 3;

    auto issue = [&](int t) {
        int s = t & 1;
        uint32_t sbase = dyn_a + (uint32_t)s * STAGE_BYTES;
        if (tid == 0) {
            uint32_t mb = mb0 + 8 * s;
            asm volatile("mbarrier.arrive.expect_tx.shared.b64 _, [%0], %1;"
                         :: "r"(mb), "r"(W_ALL_BYTES) : "memory");
            asm volatile(
                "cp.async.bulk.tensor.2d.shared::cta.global.tile.mbarrier::complete_tx::bytes "
                "[%0], [%1, {%2, %3}], [%4];"
                :: "r"(sbase), "l"(&tmap), "r"(t * KT), "r"(pos0 * 64), "r"(mb) : "memory");
        }
        int K = t * KT + xrow;
        int u = (int)(((unsigned)K * 0xAAABu) >> 17);   // K/3
        int j = K - u * 3 + pg;
        int off = voff[u * 6 + j];
        const __half* sh = g_xh + (off < 0 ? 0 : off) + xch * 8;
        const __half* sl = g_xl + (off < 0 ? 0 : off) + xch * 8;
        int sz = off < 0 ? 0 : 16;
        uint32_t xb = sbase + W_ALL_BYTES + (uint32_t)pg * X_POS_BYTES
                      + (uint32_t)(xrow * XR + xch * 8) * 2;
        CPA16(xb, sh, sz);
        CPA16(xb + X_ARR_BYTES, sl, sz);
    };

    float acc[2][2][4];
#pragma unroll
    for (int mt = 0; mt < 2; ++mt)
#pragma unroll
        for (int n = 0; n < 2; ++n)
#pragma unroll
            for (int c = 0; c < 4; ++c) acc[mt][n][c] = 0.f;

    issue(0); CPA_COMMIT();
    issue(1); CPA_COMMIT();

    // t-invariant fragment offsets
    uint32_t a_off[2][2];    // [k16][mt], relative to X pos block (hi)
#pragma unroll
    for (int k16 = 0; k16 < 2; ++k16) {
        int lrow = k16 * 16 + ((lane & 16) >> 1) + (lane & 7);
#pragma unroll
        for (int mt = 0; mt < 2; ++mt)
            a_off[k16][mt] = (uint32_t)(lrow * XR + mt * 16 + (lane & 8)) * 2;
    }
    uint32_t b_off[2][2][2]; // [k16][n][ko], relative to W pos block
    int co_n[2];
#pragma unroll
    for (int n = 0; n < 2; ++n) {
        co_n[n] = (nh * 2 + n) * 8 + g;
#pragma unroll
        for (int k16 = 0; k16 < 2; ++k16)
#pragma unroll
            for (int ko = 0; ko < 2; ++ko)
                b_off[k16][n][ko] = (uint32_t)co_n[n] * 128
                    + (uint32_t)((((k16 * 16 + 2 * tq) * 4) + ko * 32) ^ ((co_n[n] & 7) << 4));
    }

    for (int t = 0; t < NTILES; ++t) {
        int s = t & 1;
        uint32_t sbase = dyn_a + (uint32_t)s * STAGE_BYTES;
        uint32_t sbW = sbase + (uint32_t)pg * W_POS_BYTES;
        uint32_t sbX = sbase + W_ALL_BYTES + (uint32_t)pg * X_POS_BYTES;

        if (tid < 32) {   // warp 0 polls TMA mbarrier
            uint32_t mb = mb0 + 8 * s;
            uint32_t ph = (t >> 1) & 1;
            asm volatile(
                "{ .reg .pred P;\n\t"
                "WL%=: mbarrier.try_wait.parity.acquire.cta.shared::cta.b64 P, [%0], %1, 0x989680;\n\t"
                "@P bra WD%=;\n\t"
                "bra WL%=;\n\t"
                "WD%=: }"
                :: "r"(mb), "r"(ph) : "memory");
        }
        CPA_WAIT1();
        __syncthreads();

#pragma unroll
        for (int k16 = 0; k16 < 2; ++k16) {
            uint32_t ah[2][4], al[2][4];
#pragma unroll
            for (int mt = 0; mt < 2; ++mt) {
                uint32_t a_addr = sbX + a_off[k16][mt];
                LDSMT4(ah[mt], a_addr);
                LDSMT4(al[mt], a_addr + X_ARR_BYTES);
            }
#pragma unroll
            for (int n = 0; n < 2; ++n) {
                uint32_t bh[2];
#pragma unroll
                for (int ko = 0; ko < 2; ++ko) {
                    float2 f;
                    asm volatile("ld.shared.v2.f32 {%0, %1}, [%2];"
                                 : "=f"(f.x), "=f"(f.y) : "r"(sbW + b_off[k16][n][ko]));
                    asm("cvt.rn.f16x2.f32 %0, %1, %2;" : "=r"(bh[ko]) : "f"(f.y), "f"(f.x));
                }
#pragma unroll
                for (int mt = 0; mt < 2; ++mt) {
                    MMAH(acc[mt][n], ah[mt], bh);   // xh * w
                    MMAH(acc[mt][n], al[mt], bh);   // xl * w  (xh*wl dropped: ~2.8e-4)
                }
            }
        }
        __syncthreads();   // all reads of stage s done before refill
        if (t + 2 < NTILES) issue(t + 2);
        CPA_COMMIT();
    }

    // ---- epilogue: smem transpose to [b*64+co][pos4], coalesced STG.128 ----
    CPA_WAIT0();
    __syncthreads();
    float* ex = (float*)dyn;   // 32 KB
#pragma unroll
    for (int mt = 0; mt < 2; ++mt)
#pragma unroll
        for (int n = 0; n < 2; ++n)
#pragma unroll
            for (int c = 0; c < 4; ++c) {
                int b  = mt * 16 + ((c >> 1) << 3) + g;
                int co = (nh * 2 + n) * 8 + 2 * tq + (c & 1);
                ex[(b * 64 + co) * 4 + pg] = acc[mt][n][c] + sbias[pg * 64 + co];
            }
    __syncthreads();
#pragma unroll
    for (int i = 0; i < 4; ++i) {
        int bc = tid + 512 * i;
        float4 v = *(const float4*)(ex + bc * 4);
        *(float4*)(out + (size_t)bc * 1024 + pos0) = v;
    }
}

typedef CUresult (*EncodeTiledFn)(
    CUtensorMap*, CUtensorMapDataType, cuuint32_t, void*,
    const cuuint64_t*, const cuuint64_t*, const cuuint32_t*, const cuuint32_t*,
    CUtensorMapInterleave, CUtensorMapSwizzle, CUtensorMapL2promotion,
    CUtensorMapFloatOOBfill);

extern "C" void kernel_launch(void* const* d_in, const int* in_sizes, int n_in,
                              void* d_out, int out_size) {
    const float* x    = (const float*)d_in[0];
    const float* wgt  = (const float*)d_in[1];
    const float* bias = (const float*)d_in[2];
    float* out = (float*)d_out;

    void* fn = nullptr;
    cudaDriverEntryPointQueryResult qr;
    cudaGetDriverEntryPoint("cuTensorMapEncodeTiled", &fn, cudaEnableDefault, &qr);
    CUtensorMap tmap;
    cuuint64_t dims[2]    = {576, 65536};
    cuuint64_t strides[1] = {576 * 4};
    cuuint32_t box[2]     = {32, 256};     // 32 k x 256 rows (4 pos x 64 co)
    cuuint32_t es[2]      = {1, 1};
    ((EncodeTiledFn)fn)(&tmap, CU_TENSOR_MAP_DATA_TYPE_FLOAT32, 2, (void*)wgt,
                        dims, strides, box, es,
                        CU_TENSOR_MAP_INTERLEAVE_NONE, CU_TENSOR_MAP_SWIZZLE_128B,
                        CU_TENSOR_MAP_L2_PROMOTION_L2_128B,
                        CU_TENSOR_MAP_FLOAT_OOB_FILL_NONE);

    cudaFuncSetAttribute(local2d_mma, cudaFuncAttributeMaxDynamicSharedMemorySize, SMEM_TOTAL);
    transpose_x_kernel<<<CIN * HW, 256>>>(x);
    local2d_mma<<<256, 512, SMEM_TOTAL>>>(tmap, bias, out);
}